// round 9
// baseline (speedup 1.0000x reference)
#include <cuda_runtime.h>
#include <cuda_bf16.h>
#include <math.h>
#include <stdint.h>

#define FEAT_I 512
#define H_DIM  1024
#define CODE   640
#define CODE_G 320
#define B_SZ   8
#define T_SZ   4096
#define N_TOK  32768

#define DELTA   0.008f
#define FIXMAX  16384
#define FB      8

// ---------------- scratch (static device globals; no allocation) -----------
__device__ __nv_bfloat16 g_xb[(size_t)N_TOK * FEAT_I];
__device__ __nv_bfloat16 g_w1b[(size_t)H_DIM * FEAT_I];
__device__ __nv_bfloat16 g_w2b[(size_t)CODE * H_DIM];
__device__ __nv_bfloat16 g_hb[(size_t)N_TOK * H_DIM];
__device__ __nv_bfloat16 g_lb[(size_t)N_TOK * CODE];
__device__ int g_idx[N_TOK * 2];
__device__ int g_fixcnt[2];
__device__ int g_fixlist[2][FIXMAX];

// ---------------- helpers ---------------------------------------------------
__device__ __forceinline__ uint32_t smem_u32(const void* p) {
    uint32_t a;
    asm("{ .reg .u64 t; cvta.to.shared.u64 t, %1; cvt.u32.u64 %0, t; }"
        : "=r"(a) : "l"(p));
    return a;
}

__device__ __forceinline__ void ldmx4(uint32_t* r, uint32_t addr) {
    asm volatile("ldmatrix.sync.aligned.m8n8.x4.shared.b16 {%0,%1,%2,%3}, [%4];"
                 : "=r"(r[0]), "=r"(r[1]), "=r"(r[2]), "=r"(r[3]) : "r"(addr));
}

__device__ __forceinline__ void mma16816(float* d, const uint32_t* a,
                                         uint32_t b0, uint32_t b1) {
    asm volatile(
        "mma.sync.aligned.m16n8k16.row.col.f32.bf16.bf16.f32 "
        "{%0,%1,%2,%3}, {%4,%5,%6,%7}, {%8,%9}, {%0,%1,%2,%3};"
        : "+f"(d[0]), "+f"(d[1]), "+f"(d[2]), "+f"(d[3])
        : "r"(a[0]), "r"(a[1]), "r"(a[2]), "r"(a[3]), "r"(b0), "r"(b1));
}

// ---------------- transpose fp32 -> bf16: OUT[c][r] = IN[r][c] --------------
__global__ void transpose_bf16_kernel(const float* __restrict__ in,
                                      __nv_bfloat16* __restrict__ out,
                                      int R, int C, size_t ibs, size_t obs)
{
    __shared__ float tile[32][33];
    in += (size_t)blockIdx.z * ibs;
    const size_t ob = (size_t)blockIdx.z * obs;
    const int c0 = blockIdx.x * 32, r0 = blockIdx.y * 32;
    const int tx = threadIdx.x, ty = threadIdx.y;
#pragma unroll
    for (int j = 0; j < 4; j++)
        tile[ty + 8 * j][tx] = in[(size_t)(r0 + ty + 8 * j) * C + c0 + tx];
    __syncthreads();
#pragma unroll
    for (int j = 0; j < 4; j++)
        out[ob + (size_t)(c0 + ty + 8 * j) * R + r0 + tx] =
            __float2bfloat16(tile[tx][ty + 8 * j]);
}

// ---------------- bf16 HMMA GEMM (swizzled smem + ldmatrix) -----------------
// O[m][n] = act(sum_k A[m][k]*B[n][k] + bias[n]);  A=[M][K], B=[N][K], bf16.
#define BM 128
#define BN 128
#define BK 32
#define STG_A  8192            // 128 rows * 64B
#define STG    16384
#define NSTAGE 4
#define PIPE_SMEM (NSTAGE * STG)   // 65536

template<int K, bool RELU>
__global__ void __launch_bounds__(256)
gemm_bf16_kernel(const __nv_bfloat16* __restrict__ A,
                 const __nv_bfloat16* __restrict__ Bw,
                 const float* __restrict__ bias,
                 __nv_bfloat16* __restrict__ O, int ldO)
{
    extern __shared__ char smem[];
    const uint32_t sb = smem_u32(smem);
    const int tid = threadIdx.x, lane = tid & 31, wid = tid >> 5;
    const int m0 = blockIdx.y * BM, n0 = blockIdx.x * BN;
    const int mbase = (wid & 3) * 32, nbase = (wid >> 2) * 64;

    // ---- cp.async mapping: row = tid>>1, chunks c0=(tid&1)*2, c0+1 ----
    const int ldr = tid >> 1;
    const int c0c = (tid & 1) * 2;
    const int lsw = (ldr >> 1) & 3;
    const uint64_t gA = (uint64_t)__cvta_generic_to_global(A) +
                        ((size_t)(m0 + ldr) * K + (size_t)c0c * 8) * 2;
    const uint64_t gB = (uint64_t)__cvta_generic_to_global(Bw) +
                        ((size_t)(n0 + ldr) * K + (size_t)c0c * 8) * 2;
    const uint32_t dA0 = sb + ldr * 64 + (((c0c)     ^ lsw) << 4);
    const uint32_t dA1 = sb + ldr * 64 + (((c0c + 1) ^ lsw) << 4);
    const uint32_t dB0 = dA0 + STG_A;
    const uint32_t dB1 = dA1 + STG_A;

    auto issue = [&](int c) {
        const uint32_t o = (uint32_t)(c & 3) * STG;
        const uint64_t ga = gA + (size_t)c * BK * 2;
        const uint64_t gb = gB + (size_t)c * BK * 2;
        asm volatile(
            "cp.async.cg.shared.global [%0], [%1], 16;\n\t"
            "cp.async.cg.shared.global [%2], [%3], 16;\n\t"
            "cp.async.cg.shared.global [%4], [%5], 16;\n\t"
            "cp.async.cg.shared.global [%6], [%7], 16;\n\t"
            :: "r"(dA0 + o), "l"(ga), "r"(dA1 + o), "l"(ga + 16),
               "r"(dB0 + o), "l"(gb), "r"(dB1 + o), "l"(gb + 16)
            : "memory");
        asm volatile("cp.async.commit_group;" ::: "memory");
    };

    // ---- ldmatrix lane addressing (stage-relative) ----
    const int rA0 = mbase + (lane & 15);
    const int rA1 = rA0 + 16;
    const uint32_t aOff0 = sb + rA0 * 64;
    const uint32_t aOff1 = sb + rA1 * 64;
    const int aSw0 = (rA0 >> 1) & 3, aSw1 = (rA1 >> 1) & 3;
    const int hA = lane >> 4;                        // k-half for A
    const int rBb = nbase + ((lane >> 4) << 3) + (lane & 7);
    const int hB = (lane >> 3) & 1;                  // k-half for B
    uint32_t bOff[4];
    int bSw[4];
#pragma unroll
    for (int jj = 0; jj < 4; jj++) {
        const int rB = rBb + 16 * jj;
        bOff[jj] = sb + STG_A + rB * 64;
        bSw[jj] = (rB >> 1) & 3;
    }

    float acc[2][8][4];
#pragma unroll
    for (int i = 0; i < 2; i++)
#pragma unroll
        for (int j = 0; j < 8; j++)
#pragma unroll
            for (int r = 0; r < 4; r++) acc[i][j][r] = 0.f;

    issue(0); issue(1); issue(2);

    const int NC = K / BK;
#pragma unroll 1
    for (int c = 0; c < NC; c++) {
        asm volatile("cp.async.wait_group 2;" ::: "memory");
        __syncthreads();
        if (c + 3 < NC) issue(c + 3);
        else asm volatile("cp.async.commit_group;" ::: "memory");

        const uint32_t bb = (uint32_t)(c & 3) * STG;
#pragma unroll
        for (int kk = 0; kk < 2; kk++) {
            uint32_t af0[4], af1[4], bf[4][4];
            const int ca = kk * 2 + hA;
            ldmx4(af0, bb + aOff0 + ((ca ^ aSw0) << 4));
            ldmx4(af1, bb + aOff1 + ((ca ^ aSw1) << 4));
            const int cb = kk * 2 + hB;
#pragma unroll
            for (int jj = 0; jj < 4; jj++)
                ldmx4(bf[jj], bb + bOff[jj] + ((cb ^ bSw[jj]) << 4));
#pragma unroll
            for (int j = 0; j < 8; j++) {
                const uint32_t b0 = bf[j >> 1][(j & 1) * 2];
                const uint32_t b1v = bf[j >> 1][(j & 1) * 2 + 1];
                mma16816(acc[0][j], af0, b0, b1v);
                mma16816(acc[1][j], af1, b0, b1v);
            }
        }
    }

    // epilogue: bias (+relu), stage bf16 in smem, 16B-coalesced stores
    __syncthreads();
    const int qr = lane >> 2;
    __nv_bfloat16* st = (__nv_bfloat16*)smem;
#pragma unroll
    for (int j = 0; j < 8; j++) {
        const int nb = nbase + 8 * j + (lane & 3) * 2;
        const float2 bs = *(const float2*)(bias + n0 + nb);
#pragma unroll
        for (int i = 0; i < 2; i++) {
            float v0 = acc[i][j][0] + bs.x, v1 = acc[i][j][1] + bs.y;
            float v2 = acc[i][j][2] + bs.x, v3 = acc[i][j][3] + bs.y;
            if (RELU) {
                v0 = fmaxf(v0, 0.f); v1 = fmaxf(v1, 0.f);
                v2 = fmaxf(v2, 0.f); v3 = fmaxf(v3, 0.f);
            }
            const int mr = mbase + 16 * i + qr;
            *(__nv_bfloat162*)(st + mr * 136 + nb) = __floats2bfloat162_rn(v0, v1);
            *(__nv_bfloat162*)(st + (mr + 8) * 136 + nb) = __floats2bfloat162_rn(v2, v3);
        }
    }
    __syncthreads();
#pragma unroll
    for (int v = 0; v < 8; v++) {
        const int idx = tid + v * 256;
        const int row = idx >> 4, c8 = (idx & 15) * 8;
        *(uint4*)(O + (size_t)(m0 + row) * ldO + n0 + c8) =
            *(const uint4*)(st + row * 136 + c8);
    }
}

// ---------------- gumbel + argmax with top-2 margin flag --------------------
__global__ void __launch_bounds__(256) argmax_kernel(
    const float* __restrict__ gumbel_u, float* __restrict__ idx_out_f)
{
    const int warp = (blockIdx.x * blockDim.x + threadIdx.x) >> 5;
    const int lane = threadIdx.x & 31;
    if (warp >= N_TOK * 2) return;
    const int n = warp >> 1, g = warp & 1;
    const __nv_bfloat16* lrow = g_lb + (size_t)n * CODE + g * CODE_G;
    const float* urow = gumbel_u + (size_t)n * CODE + g * CODE_G;

    float b1v = -INFINITY, b2v = -INFINITY;
    int bi = 0x7fffffff;
#pragma unroll
    for (int c = lane; c < CODE_G; c += 32) {
        float u  = urow[c];
        float gn = -__logf(-__logf(u + 1e-10f) + 1e-10f);
        float v  = __bfloat162float(lrow[c]) + gn;
        if (v > b1v) { b2v = b1v; b1v = v; bi = c; }
        else if (v > b2v) b2v = v;
    }
#pragma unroll
    for (int off = 16; off > 0; off >>= 1) {
        float o1 = __shfl_down_sync(0xffffffffu, b1v, off);
        float o2 = __shfl_down_sync(0xffffffffu, b2v, off);
        int   oi = __shfl_down_sync(0xffffffffu, bi, off);
        if (o1 > b1v || (o1 == b1v && oi < bi)) {
            b2v = fmaxf(b1v, o2); b1v = o1; bi = oi;
        } else {
            b2v = fmaxf(b2v, o1);
        }
    }
    if (lane == 0) {
        g_idx[warp] = bi;
        idx_out_f[warp] = (float)bi;
        if (b1v - b2v < DELTA) {
            int p = atomicAdd(&g_fixcnt[g], 1);
            if (p < FIXMAX) g_fixlist[g][p] = warp;
        }
    }
}

// ---------------- exact fp32 fixup, batched FB slots (same group) -----------
#define FIX_SMEM (FB * FEAT_I * 4 + FB * H_DIM * 4 + 64)
__global__ void __launch_bounds__(256) fixup_kernel(
    const float* __restrict__ series, const float* __restrict__ W1,
    const float* __restrict__ b1, const float* __restrict__ W2,
    const float* __restrict__ b2, const float* __restrict__ gumbel_u,
    float* __restrict__ idx_out_f)
{
    extern __shared__ char sm[];
    float* xs = (float*)sm;                       // [FEAT_I][FB]
    float* hs = xs + FB * FEAT_I;                 // [FB][H_DIM]
    int* slots = (int*)(hs + FB * H_DIM);         // [FB]
    const int tid = threadIdx.x, lane = tid & 31, w = tid >> 5;

    const int cnt0 = min(g_fixcnt[0], FIXMAX);
    const int cnt1 = min(g_fixcnt[1], FIXMAX);
    const int nb0 = (cnt0 + FB - 1) / FB, nb1 = (cnt1 + FB - 1) / FB;

    for (int task = blockIdx.x; task < nb0 + nb1; task += gridDim.x) {
        const int g = (task < nb0) ? 0 : 1;
        const int base = ((task < nb0) ? task : task - nb0) * FB;
        const int cnt = g ? cnt1 : cnt0;
        const int ns = min(FB, cnt - base);
        const int gbase = g * CODE_G;

        __syncthreads();
        if (tid < FB)
            slots[tid] = g_fixlist[g][base + ((tid < ns) ? tid : 0)];
        __syncthreads();

        // exact x rows, transposed layout xs[k*FB + s]
        for (int i = tid; i < FB * FEAT_I; i += 256) {
            const int s = i & (FB - 1), k = i >> 3;
            const int n = slots[s] >> 1;
            const int bb = n >> 12, tt = n & 4095;
            xs[k * FB + s] = series[((size_t)bb * FEAT_I + k) * T_SZ + tt];
        }
        __syncthreads();

        // exact h rows (8 slots share each W1 element)
        for (int j = tid; j < H_DIM; j += 256) {
            float a[FB];
            const float bj = b1[j];
#pragma unroll
            for (int s = 0; s < FB; s++) a[s] = bj;
            for (int k = 0; k < FEAT_I; k++) {
                const float wv = W1[(size_t)k * H_DIM + j];
                const float4 x0 = *(const float4*)&xs[k * FB];
                const float4 x1 = *(const float4*)&xs[k * FB + 4];
                a[0] = fmaf(x0.x, wv, a[0]); a[1] = fmaf(x0.y, wv, a[1]);
                a[2] = fmaf(x0.z, wv, a[2]); a[3] = fmaf(x0.w, wv, a[3]);
                a[4] = fmaf(x1.x, wv, a[4]); a[5] = fmaf(x1.y, wv, a[5]);
                a[6] = fmaf(x1.z, wv, a[6]); a[7] = fmaf(x1.w, wv, a[7]);
            }
#pragma unroll
            for (int s = 0; s < FB; s++) hs[s * H_DIM + j] = fmaxf(a[s], 0.f);
        }
        __syncthreads();

        // logits + exact gumbel + argmax: one warp per slot
        const int slot = slots[w];
        const int n = slot >> 1;
        float bv = -INFINITY;
        int bi = 0x7fffffff;
        for (int c = lane; c < CODE_G; c += 32) {
            float a = b2[gbase + c];
            const float* hrow = hs + w * H_DIM;
            const float* wcol = W2 + gbase + c;
            for (int k = 0; k < H_DIM; k += 4) {
                a = fmaf(hrow[k],     wcol[(size_t)(k)     * CODE], a);
                a = fmaf(hrow[k + 1], wcol[(size_t)(k + 1) * CODE], a);
                a = fmaf(hrow[k + 2], wcol[(size_t)(k + 2) * CODE], a);
                a = fmaf(hrow[k + 3], wcol[(size_t)(k + 3) * CODE], a);
            }
            const float u = gumbel_u[(size_t)n * CODE + gbase + c];
            const float v = a + (-logf(-logf(u + 1e-10f) + 1e-10f));
            if (v > bv) { bv = v; bi = c; }
        }
#pragma unroll
        for (int off = 16; off > 0; off >>= 1) {
            float ov = __shfl_down_sync(0xffffffffu, bv, off);
            int   oi = __shfl_down_sync(0xffffffffu, bi, off);
            if (ov > bv || (ov == bv && oi < bi)) { bv = ov; bi = oi; }
        }
        if (lane == 0 && w < ns) {
            g_idx[slot] = bi;
            idx_out_f[slot] = (float)bi;
        }
    }
}

// ---------------- gather: tiled, coalesced; also resets fix counters --------
__global__ void __launch_bounds__(256) gather_kernel(
    const float* __restrict__ codebook, float* __restrict__ out)
{
    __shared__ float cb[32 * 257];
    __shared__ int   sidx[32];
    const int tid = threadIdx.x;
    if (blockIdx.x == 0 && tid == 0) { g_fixcnt[0] = 0; g_fixcnt[1] = 0; }
    const int t0 = (blockIdx.x & 127) * 32;
    const int g  = (blockIdx.x >> 7) & 1;
    const int b  = blockIdx.x >> 8;

    if (tid < 32)
        sidx[tid] = g_idx[((b << 12) + t0 + tid) * 2 + g];
    __syncthreads();

#pragma unroll
    for (int it = 0; it < 8; it++) {
        const int j = tid + it * 256;
        const int row = j >> 6, c4 = (j & 63) * 4;
        float4 v = *(const float4*)(codebook + (((size_t)g * CODE_G + sidx[row]) << 8) + c4);
        float* p = cb + row * 257 + c4;
        p[0] = v.x; p[1] = v.y; p[2] = v.z; p[3] = v.w;
    }
    __syncthreads();

#pragma unroll
    for (int it = 0; it < 8; it++) {
        const int j = tid + it * 256;
        const int f = j >> 3, t4 = (j & 7) * 4;
        float4 v;
        v.x = cb[(t4 + 0) * 257 + f];
        v.y = cb[(t4 + 1) * 257 + f];
        v.z = cb[(t4 + 2) * 257 + f];
        v.w = cb[(t4 + 3) * 257 + f];
        *(float4*)(out + ((size_t)(b * 512 + g * 256 + f) << 12) + t0 + t4) = v;
    }
}

// ---------------------------------------------------------------------------
extern "C" void kernel_launch(void* const* d_in, const int* in_sizes, int n_in,
                              void* d_out, int out_size)
{
    const float* series   = (const float*)d_in[0];
    const float* gumbel_u = (const float*)d_in[1];
    const float* W1       = (const float*)d_in[2];
    const float* b1       = (const float*)d_in[3];
    const float* W2       = (const float*)d_in[4];
    const float* b2       = (const float*)d_in[5];
    const float* codebook = (const float*)d_in[6];
    float* out = (float*)d_out;
    float* idx_out = out + ((size_t)out_size - (size_t)N_TOK * 2);

    __nv_bfloat16 *xb, *w1b, *w2b, *hb, *lb;
    cudaGetSymbolAddress((void**)&xb,  g_xb);
    cudaGetSymbolAddress((void**)&w1b, g_w1b);
    cudaGetSymbolAddress((void**)&w2b, g_w2b);
    cudaGetSymbolAddress((void**)&hb,  g_hb);
    cudaGetSymbolAddress((void**)&lb,  g_lb);

    cudaFuncSetAttribute(gemm_bf16_kernel<FEAT_I, true>,
                         cudaFuncAttributeMaxDynamicSharedMemorySize, PIPE_SMEM);
    cudaFuncSetAttribute(gemm_bf16_kernel<H_DIM, false>,
                         cudaFuncAttributeMaxDynamicSharedMemorySize, PIPE_SMEM);
    cudaFuncSetAttribute(fixup_kernel,
                         cudaFuncAttributeMaxDynamicSharedMemorySize, FIX_SMEM);

    // pack/transpose inputs to bf16
    transpose_bf16_kernel<<<dim3(T_SZ / 32, FEAT_I / 32, B_SZ), dim3(32, 8)>>>(
        series, xb, FEAT_I, T_SZ, (size_t)FEAT_I * T_SZ, (size_t)T_SZ * FEAT_I);
    transpose_bf16_kernel<<<dim3(H_DIM / 32, FEAT_I / 32, 1), dim3(32, 8)>>>(
        W1, w1b, FEAT_I, H_DIM, 0, 0);
    transpose_bf16_kernel<<<dim3(CODE / 32, H_DIM / 32, 1), dim3(32, 8)>>>(
        W2, w2b, H_DIM, CODE, 0, 0);

    // GEMM1: h = relu(X W1 + b1)  (bf16 out)
    gemm_bf16_kernel<FEAT_I, true><<<dim3(H_DIM / BN, N_TOK / BM), 256, PIPE_SMEM>>>(
        xb, w1b, b1, hb, H_DIM);
    // GEMM2: logits = h W2 + b2   (bf16 out)
    gemm_bf16_kernel<H_DIM, false><<<dim3(CODE / BN, N_TOK / BM), 256, PIPE_SMEM>>>(
        hb, w2b, b2, lb, CODE);

    argmax_kernel<<<(N_TOK * 2 * 32) / 256, 256>>>(gumbel_u, idx_out);
    fixup_kernel<<<128, 256, FIX_SMEM>>>(series, W1, b1, W2, b2, gumbel_u, idx_out);
    gather_kernel<<<B_SZ * 2 * (T_SZ / 32), 256>>>(codebook, out);
}

// round 11
// speedup vs baseline: 2.0021x; 2.0021x over previous
#include <cuda_runtime.h>
#include <cuda_bf16.h>
#include <math.h>
#include <stdint.h>

#define FEAT_I 512
#define H_DIM  1024
#define CODE   640
#define CODE_G 320
#define B_SZ   8
#define T_SZ   4096
#define N_TOK  32768

#define DELTA   0.008f
#define EPS     1e-10f
#define FIXMAX  16384

// ---------------- scratch (static device globals; no allocation) -----------
__device__ __nv_bfloat16 g_xb[(size_t)N_TOK * FEAT_I];
__device__ __nv_bfloat16 g_w1b[(size_t)H_DIM * FEAT_I];
__device__ __nv_bfloat16 g_w2b[(size_t)CODE * H_DIM];
__device__ __nv_bfloat16 g_hb[(size_t)N_TOK * H_DIM];
__device__ __nv_bfloat16 g_lb[(size_t)N_TOK * CODE];
__device__ int g_idx[N_TOK * 2];
__device__ int g_fixcnt;
__device__ int g_fixlist[FIXMAX];

// ---------------- helpers ---------------------------------------------------
__device__ __forceinline__ uint32_t smem_u32(const void* p) {
    uint32_t a;
    asm("{ .reg .u64 t; cvta.to.shared.u64 t, %1; cvt.u32.u64 %0, t; }"
        : "=r"(a) : "l"(p));
    return a;
}

__device__ __forceinline__ void ldmx4(uint32_t* r, uint32_t addr) {
    asm volatile("ldmatrix.sync.aligned.m8n8.x4.shared.b16 {%0,%1,%2,%3}, [%4];"
                 : "=r"(r[0]), "=r"(r[1]), "=r"(r[2]), "=r"(r[3]) : "r"(addr));
}

__device__ __forceinline__ void mma16816(float* d, const uint32_t* a,
                                         uint32_t b0, uint32_t b1) {
    asm volatile(
        "mma.sync.aligned.m16n8k16.row.col.f32.bf16.bf16.f32 "
        "{%0,%1,%2,%3}, {%4,%5,%6,%7}, {%8,%9}, {%0,%1,%2,%3};"
        : "+f"(d[0]), "+f"(d[1]), "+f"(d[2]), "+f"(d[3])
        : "r"(a[0]), "r"(a[1]), "r"(a[2]), "r"(a[3]), "r"(b0), "r"(b1));
}

// ---------------- transpose fp32 -> bf16: OUT[c][r] = IN[r][c] --------------
__global__ void transpose_bf16_kernel(const float* __restrict__ in,
                                      __nv_bfloat16* __restrict__ out,
                                      int R, int C, size_t ibs, size_t obs)
{
    __shared__ float tile[32][33];
    in += (size_t)blockIdx.z * ibs;
    const size_t ob = (size_t)blockIdx.z * obs;
    const int c0 = blockIdx.x * 32, r0 = blockIdx.y * 32;
    const int tx = threadIdx.x, ty = threadIdx.y;
#pragma unroll
    for (int j = 0; j < 4; j++)
        tile[ty + 8 * j][tx] = in[(size_t)(r0 + ty + 8 * j) * C + c0 + tx];
    __syncthreads();
#pragma unroll
    for (int j = 0; j < 4; j++)
        out[ob + (size_t)(c0 + ty + 8 * j) * R + r0 + tx] =
            __float2bfloat16(tile[tx][ty + 8 * j]);
}

// ---------------- bf16 HMMA GEMM (swizzled smem + ldmatrix) -----------------
#define BM 128
#define BN 128
#define BK 32
#define STG_A  8192
#define STG    16384
#define NSTAGE 4
#define PIPE_SMEM (NSTAGE * STG)

template<int K, bool RELU>
__global__ void __launch_bounds__(256)
gemm_bf16_kernel(const __nv_bfloat16* __restrict__ A,
                 const __nv_bfloat16* __restrict__ Bw,
                 const float* __restrict__ bias,
                 __nv_bfloat16* __restrict__ O, int ldO)
{
    extern __shared__ char smem[];
    const uint32_t sb = smem_u32(smem);
    const int tid = threadIdx.x, lane = tid & 31, wid = tid >> 5;
    const int m0 = blockIdx.y * BM, n0 = blockIdx.x * BN;
    const int mbase = (wid & 3) * 32, nbase = (wid >> 2) * 64;

    const int ldr = tid >> 1;
    const int c0c = (tid & 1) * 2;
    const int lsw = (ldr >> 1) & 3;
    const uint64_t gA = (uint64_t)__cvta_generic_to_global(A) +
                        ((size_t)(m0 + ldr) * K + (size_t)c0c * 8) * 2;
    const uint64_t gB = (uint64_t)__cvta_generic_to_global(Bw) +
                        ((size_t)(n0 + ldr) * K + (size_t)c0c * 8) * 2;
    const uint32_t dA0 = sb + ldr * 64 + (((c0c)     ^ lsw) << 4);
    const uint32_t dA1 = sb + ldr * 64 + (((c0c + 1) ^ lsw) << 4);
    const uint32_t dB0 = dA0 + STG_A;
    const uint32_t dB1 = dA1 + STG_A;

    auto issue = [&](int c) {
        const uint32_t o = (uint32_t)(c & 3) * STG;
        const uint64_t ga = gA + (size_t)c * BK * 2;
        const uint64_t gb = gB + (size_t)c * BK * 2;
        asm volatile(
            "cp.async.cg.shared.global [%0], [%1], 16;\n\t"
            "cp.async.cg.shared.global [%2], [%3], 16;\n\t"
            "cp.async.cg.shared.global [%4], [%5], 16;\n\t"
            "cp.async.cg.shared.global [%6], [%7], 16;\n\t"
            :: "r"(dA0 + o), "l"(ga), "r"(dA1 + o), "l"(ga + 16),
               "r"(dB0 + o), "l"(gb), "r"(dB1 + o), "l"(gb + 16)
            : "memory");
        asm volatile("cp.async.commit_group;" ::: "memory");
    };

    const int rA0 = mbase + (lane & 15);
    const int rA1 = rA0 + 16;
    const uint32_t aOff0 = sb + rA0 * 64;
    const uint32_t aOff1 = sb + rA1 * 64;
    const int aSw0 = (rA0 >> 1) & 3, aSw1 = (rA1 >> 1) & 3;
    const int hA = lane >> 4;
    const int rBb = nbase + ((lane >> 4) << 3) + (lane & 7);
    const int hB = (lane >> 3) & 1;
    uint32_t bOff[4];
    int bSw[4];
#pragma unroll
    for (int jj = 0; jj < 4; jj++) {
        const int rB = rBb + 16 * jj;
        bOff[jj] = sb + STG_A + rB * 64;
        bSw[jj] = (rB >> 1) & 3;
    }

    float acc[2][8][4];
#pragma unroll
    for (int i = 0; i < 2; i++)
#pragma unroll
        for (int j = 0; j < 8; j++)
#pragma unroll
            for (int r = 0; r < 4; r++) acc[i][j][r] = 0.f;

    issue(0); issue(1); issue(2);

    const int NC = K / BK;
#pragma unroll 1
    for (int c = 0; c < NC; c++) {
        asm volatile("cp.async.wait_group 2;" ::: "memory");
        __syncthreads();
        if (c + 3 < NC) issue(c + 3);
        else asm volatile("cp.async.commit_group;" ::: "memory");

        const uint32_t bb = (uint32_t)(c & 3) * STG;
#pragma unroll
        for (int kk = 0; kk < 2; kk++) {
            uint32_t af0[4], af1[4], bf[4][4];
            const int ca = kk * 2 + hA;
            ldmx4(af0, bb + aOff0 + ((ca ^ aSw0) << 4));
            ldmx4(af1, bb + aOff1 + ((ca ^ aSw1) << 4));
            const int cb = kk * 2 + hB;
#pragma unroll
            for (int jj = 0; jj < 4; jj++)
                ldmx4(bf[jj], bb + bOff[jj] + ((cb ^ bSw[jj]) << 4));
#pragma unroll
            for (int j = 0; j < 8; j++) {
                const uint32_t b0 = bf[j >> 1][(j & 1) * 2];
                const uint32_t b1v = bf[j >> 1][(j & 1) * 2 + 1];
                mma16816(acc[0][j], af0, b0, b1v);
                mma16816(acc[1][j], af1, b0, b1v);
            }
        }
    }

    __syncthreads();
    const int qr = lane >> 2;
    __nv_bfloat16* st = (__nv_bfloat16*)smem;
#pragma unroll
    for (int j = 0; j < 8; j++) {
        const int nb = nbase + 8 * j + (lane & 3) * 2;
        const float2 bs = *(const float2*)(bias + n0 + nb);
#pragma unroll
        for (int i = 0; i < 2; i++) {
            float v0 = acc[i][j][0] + bs.x, v1 = acc[i][j][1] + bs.y;
            float v2 = acc[i][j][2] + bs.x, v3 = acc[i][j][3] + bs.y;
            if (RELU) {
                v0 = fmaxf(v0, 0.f); v1 = fmaxf(v1, 0.f);
                v2 = fmaxf(v2, 0.f); v3 = fmaxf(v3, 0.f);
            }
            const int mr = mbase + 16 * i + qr;
            *(__nv_bfloat162*)(st + mr * 136 + nb) = __floats2bfloat162_rn(v0, v1);
            *(__nv_bfloat162*)(st + (mr + 8) * 136 + nb) = __floats2bfloat162_rn(v2, v3);
        }
    }
    __syncthreads();
#pragma unroll
    for (int v = 0; v < 8; v++) {
        const int idx = tid + v * 256;
        const int row = idx >> 4, c8 = (idx & 15) * 8;
        *(uint4*)(O + (size_t)(m0 + row) * ldO + n0 + c8) =
            *(const uint4*)(st + row * 136 + c8);
    }
}

// ---------------- screened gumbel + argmax ----------------------------------
// g(u) = -log(-log(u+eps)+eps) is monotone increasing in u. Per row compute
// U=max u, Lmax/Lmin of logits; only u >= g^{-1}(g(U)-(Lmax-Lmin)-DELTA-slack)
// can be within DELTA of the max -> exact g for ~4 of 320 codes.
__global__ void __launch_bounds__(256) argmax_kernel(
    const float* __restrict__ gumbel_u, float* __restrict__ idx_out_f)
{
    const int warp = (blockIdx.x * blockDim.x + threadIdx.x) >> 5;
    const int lane = threadIdx.x & 31;
    if (warp >= N_TOK * 2) return;
    const int n = warp >> 1, g = warp & 1;
    const __nv_bfloat16* lrow = g_lb + (size_t)n * CODE + g * CODE_G;
    const float* urow = gumbel_u + (size_t)n * CODE + g * CODE_G;

    float u[10], l[10];
#pragma unroll
    for (int j = 0; j < 10; j++) {
        u[j] = urow[lane + 32 * j];
        l[j] = __bfloat162float(lrow[lane + 32 * j]);
    }
    float umax = u[0], lmax = l[0], lmin = l[0];
#pragma unroll
    for (int j = 1; j < 10; j++) {
        umax = fmaxf(umax, u[j]);
        lmax = fmaxf(lmax, l[j]);
        lmin = fminf(lmin, l[j]);
    }
#pragma unroll
    for (int off = 16; off > 0; off >>= 1) {
        umax = fmaxf(umax, __shfl_xor_sync(0xffffffffu, umax, off));
        lmax = fmaxf(lmax, __shfl_xor_sync(0xffffffffu, lmax, off));
        lmin = fminf(lmin, __shfl_xor_sync(0xffffffffu, lmin, off));
    }
    // threshold (all lanes compute; uniform)
    const float gU   = -__logf(-__logf(umax + EPS) + EPS);
    const float gthr = gU - (lmax - lmin) - DELTA - 0.02f;
    const float wv   = __expf(-gthr);                 // target -log(u+eps)+eps
    float uthr = __expf(-(wv - EPS)) - EPS;
    uthr = uthr - fabsf(uthr) * 4e-6f - 1e-7f;        // expf-error slack

    float b1v = -INFINITY, b2v = -INFINITY;
    int bi = 0x7fffffff;
#pragma unroll
    for (int j = 0; j < 10; j++) {
        if (u[j] >= uthr) {
            const float gn = -__logf(-__logf(u[j] + EPS) + EPS);
            const float v = l[j] + gn;
            if (v > b1v) { b2v = b1v; b1v = v; bi = lane + 32 * j; }
            else if (v > b2v) b2v = v;
        }
    }
#pragma unroll
    for (int off = 16; off > 0; off >>= 1) {
        float o1 = __shfl_down_sync(0xffffffffu, b1v, off);
        float o2 = __shfl_down_sync(0xffffffffu, b2v, off);
        int   oi = __shfl_down_sync(0xffffffffu, bi, off);
        if (o1 > b1v || (o1 == b1v && oi < bi)) {
            b2v = fmaxf(b1v, o2); b1v = o1; bi = oi;
        } else {
            b2v = fmaxf(b2v, o1);
        }
    }
    if (lane == 0) {
        g_idx[warp] = bi;
        idx_out_f[warp] = (float)bi;
        if (b1v - b2v < DELTA) {
            int p = atomicAdd(&g_fixcnt, 1);
            if (p < FIXMAX) g_fixlist[p] = warp;
        }
    }
}

// ---------------- exact fp32 fixup (per-slot, proven) -----------------------
__global__ void __launch_bounds__(256) fixup_kernel(
    const float* __restrict__ series, const float* __restrict__ W1,
    const float* __restrict__ b1, const float* __restrict__ W2,
    const float* __restrict__ b2, const float* __restrict__ gumbel_u,
    float* __restrict__ idx_out_f)
{
    __shared__ float xs[FEAT_I];
    __shared__ float hs[H_DIM];
    __shared__ float rv[256];
    __shared__ int   ri[256];
    const int tid = threadIdx.x;
    const int cnt = min(g_fixcnt, FIXMAX);

    for (int e = blockIdx.x; e < cnt; e += gridDim.x) {
        const int slot = g_fixlist[e];
        const int n = slot >> 1, g = slot & 1;
        const int b = n >> 12, t = n & 4095;
        const int gbase = g * CODE_G;

        for (int k = tid; k < FEAT_I; k += 256)
            xs[k] = series[((size_t)b * FEAT_I + k) * T_SZ + t];
        __syncthreads();

        for (int j = tid; j < H_DIM; j += 256) {
            float a = b1[j];
            for (int k = 0; k < FEAT_I; k++)
                a = fmaf(xs[k], W1[(size_t)k * H_DIM + j], a);
            hs[j] = fmaxf(a, 0.f);
        }
        __syncthreads();

        float v0 = -INFINITY, v1 = -INFINITY;
        {
            float a = b2[gbase + tid];
            for (int k = 0; k < H_DIM; k++)
                a = fmaf(hs[k], W2[(size_t)k * CODE + gbase + tid], a);
            float uu = gumbel_u[(size_t)n * CODE + gbase + tid];
            v0 = a + (-logf(-logf(uu + EPS) + EPS));
        }
        if (tid < CODE_G - 256) {
            const int c = tid + 256;
            float a = b2[gbase + c];
            for (int k = 0; k < H_DIM; k++)
                a = fmaf(hs[k], W2[(size_t)k * CODE + gbase + c], a);
            float uu = gumbel_u[(size_t)n * CODE + gbase + c];
            v1 = a + (-logf(-logf(uu + EPS) + EPS));
        }
        float bv = v0; int bi = tid;
        if (v1 > bv) { bv = v1; bi = tid + 256; }
        rv[tid] = bv; ri[tid] = bi;
        __syncthreads();
        for (int s = 128; s > 0; s >>= 1) {
            if (tid < s) {
                if (rv[tid + s] > rv[tid] ||
                    (rv[tid + s] == rv[tid] && ri[tid + s] < ri[tid])) {
                    rv[tid] = rv[tid + s]; ri[tid] = ri[tid + s];
                }
            }
            __syncthreads();
        }
        if (tid == 0) {
            g_idx[slot] = ri[0];
            idx_out_f[slot] = (float)ri[0];
        }
        __syncthreads();
    }
}

// ---------------- gather: tiled, coalesced; resets fix counter --------------
__global__ void __launch_bounds__(256) gather_kernel(
    const float* __restrict__ codebook, float* __restrict__ out)
{
    __shared__ float cb[32 * 257];
    __shared__ int   sidx[32];
    const int tid = threadIdx.x;
    if (blockIdx.x == 0 && tid == 0) g_fixcnt = 0;
    const int t0 = (blockIdx.x & 127) * 32;
    const int g  = (blockIdx.x >> 7) & 1;
    const int b  = blockIdx.x >> 8;

    if (tid < 32)
        sidx[tid] = g_idx[((b << 12) + t0 + tid) * 2 + g];
    __syncthreads();

#pragma unroll
    for (int it = 0; it < 8; it++) {
        const int j = tid + it * 256;
        const int row = j >> 6, c4 = (j & 63) * 4;
        float4 v = *(const float4*)(codebook + (((size_t)g * CODE_G + sidx[row]) << 8) + c4);
        float* p = cb + row * 257 + c4;
        p[0] = v.x; p[1] = v.y; p[2] = v.z; p[3] = v.w;
    }
    __syncthreads();

#pragma unroll
    for (int it = 0; it < 8; it++) {
        const int j = tid + it * 256;
        const int f = j >> 3, t4 = (j & 7) * 4;
        float4 v;
        v.x = cb[(t4 + 0) * 257 + f];
        v.y = cb[(t4 + 1) * 257 + f];
        v.z = cb[(t4 + 2) * 257 + f];
        v.w = cb[(t4 + 3) * 257 + f];
        *(float4*)(out + ((size_t)(b * 512 + g * 256 + f) << 12) + t0 + t4) = v;
    }
}

// ---------------------------------------------------------------------------
extern "C" void kernel_launch(void* const* d_in, const int* in_sizes, int n_in,
                              void* d_out, int out_size)
{
    const float* series   = (const float*)d_in[0];
    const float* gumbel_u = (const float*)d_in[1];
    const float* W1       = (const float*)d_in[2];
    const float* b1       = (const float*)d_in[3];
    const float* W2       = (const float*)d_in[4];
    const float* b2       = (const float*)d_in[5];
    const float* codebook = (const float*)d_in[6];
    float* out = (float*)d_out;
    float* idx_out = out + ((size_t)out_size - (size_t)N_TOK * 2);

    __nv_bfloat16 *xb, *w1b, *w2b, *hb, *lb;
    cudaGetSymbolAddress((void**)&xb,  g_xb);
    cudaGetSymbolAddress((void**)&w1b, g_w1b);
    cudaGetSymbolAddress((void**)&w2b, g_w2b);
    cudaGetSymbolAddress((void**)&hb,  g_hb);
    cudaGetSymbolAddress((void**)&lb,  g_lb);

    cudaFuncSetAttribute(gemm_bf16_kernel<FEAT_I, true>,
                         cudaFuncAttributeMaxDynamicSharedMemorySize, PIPE_SMEM);
    cudaFuncSetAttribute(gemm_bf16_kernel<H_DIM, false>,
                         cudaFuncAttributeMaxDynamicSharedMemorySize, PIPE_SMEM);

    transpose_bf16_kernel<<<dim3(T_SZ / 32, FEAT_I / 32, B_SZ), dim3(32, 8)>>>(
        series, xb, FEAT_I, T_SZ, (size_t)FEAT_I * T_SZ, (size_t)T_SZ * FEAT_I);
    transpose_bf16_kernel<<<dim3(H_DIM / 32, FEAT_I / 32, 1), dim3(32, 8)>>>(
        W1, w1b, FEAT_I, H_DIM, 0, 0);
    transpose_bf16_kernel<<<dim3(CODE / 32, H_DIM / 32, 1), dim3(32, 8)>>>(
        W2, w2b, H_DIM, CODE, 0, 0);

    gemm_bf16_kernel<FEAT_I, true><<<dim3(H_DIM / BN, N_TOK / BM), 256, PIPE_SMEM>>>(
        xb, w1b, b1, hb, H_DIM);
    gemm_bf16_kernel<H_DIM, false><<<dim3(CODE / BN, N_TOK / BM), 256, PIPE_SMEM>>>(
        hb, w2b, b2, lb, CODE);

    argmax_kernel<<<(N_TOK * 2 * 32) / 256, 256>>>(gumbel_u, idx_out);
    fixup_kernel<<<256, 256>>>(series, W1, b1, W2, b2, gumbel_u, idx_out);
    gather_kernel<<<B_SZ * 2 * (T_SZ / 32), 256>>>(codebook, out);
}

// round 16
// speedup vs baseline: 3.9213x; 1.9586x over previous
#include <cuda_runtime.h>
#include <cuda_bf16.h>
#include <math.h>
#include <stdint.h>

#define FEAT_I 512
#define H_DIM  1024
#define CODE   640
#define CODE_G 320
#define B_SZ   8
#define T_SZ   4096
#define N_TOK  32768

#define DELTA   0.008f
#define EPS     1e-10f
#define FIXMAX  16384

// ---------------- scratch (static device globals; no allocation) -----------
__device__ __nv_bfloat16 g_xb[(size_t)N_TOK * FEAT_I];
__device__ __nv_bfloat16 g_w1b[(size_t)H_DIM * FEAT_I];
__device__ __nv_bfloat16 g_w2b[(size_t)CODE * H_DIM];
__device__ __nv_bfloat16 g_hb[(size_t)N_TOK * H_DIM];
__device__ __nv_bfloat16 g_lb[(size_t)N_TOK * CODE];
__device__ int g_idx[N_TOK * 2];
__device__ int g_fixcnt;
__device__ int g_fixlist[FIXMAX];
__device__ float g_fixx[(size_t)FIXMAX * FEAT_I];   // 32 MB
__device__ float g_fixh[(size_t)FIXMAX * H_DIM];    // 64 MB
__device__ float g_fixl[(size_t)FIXMAX * CODE];     // 40 MB

// ---------------- helpers ---------------------------------------------------
__device__ __forceinline__ uint32_t smem_u32(const void* p) {
    uint32_t a;
    asm("{ .reg .u64 t; cvta.to.shared.u64 t, %1; cvt.u32.u64 %0, t; }"
        : "=r"(a) : "l"(p));
    return a;
}

__device__ __forceinline__ void ldmx4(uint32_t* r, uint32_t addr) {
    asm volatile("ldmatrix.sync.aligned.m8n8.x4.shared.b16 {%0,%1,%2,%3}, [%4];"
                 : "=r"(r[0]), "=r"(r[1]), "=r"(r[2]), "=r"(r[3]) : "r"(addr));
}

__device__ __forceinline__ void mma16816(float* d, const uint32_t* a,
                                         uint32_t b0, uint32_t b1) {
    asm volatile(
        "mma.sync.aligned.m16n8k16.row.col.f32.bf16.bf16.f32 "
        "{%0,%1,%2,%3}, {%4,%5,%6,%7}, {%8,%9}, {%0,%1,%2,%3};"
        : "+f"(d[0]), "+f"(d[1]), "+f"(d[2]), "+f"(d[3])
        : "r"(a[0]), "r"(a[1]), "r"(a[2]), "r"(a[3]), "r"(b0), "r"(b1));
}

// ---------------- transpose fp32 -> bf16: OUT[c][r] = IN[r][c] --------------
__global__ void transpose_bf16_kernel(const float* __restrict__ in,
                                      __nv_bfloat16* __restrict__ out,
                                      int R, int C, size_t ibs, size_t obs)
{
    __shared__ float tile[32][33];
    in += (size_t)blockIdx.z * ibs;
    const size_t ob = (size_t)blockIdx.z * obs;
    const int c0 = blockIdx.x * 32, r0 = blockIdx.y * 32;
    const int tx = threadIdx.x, ty = threadIdx.y;
#pragma unroll
    for (int j = 0; j < 4; j++)
        tile[ty + 8 * j][tx] = in[(size_t)(r0 + ty + 8 * j) * C + c0 + tx];
    __syncthreads();
#pragma unroll
    for (int j = 0; j < 4; j++)
        out[ob + (size_t)(c0 + ty + 8 * j) * R + r0 + tx] =
            __float2bfloat16(tile[tx][ty + 8 * j]);
}

// ---------------- bf16 HMMA GEMM (swizzled smem + ldmatrix) -----------------
#define BM 128
#define BN 128
#define BK 32
#define STG_A  8192
#define STG    16384
#define NSTAGE 4
#define PIPE_SMEM (NSTAGE * STG)

template<int K, bool RELU>
__global__ void __launch_bounds__(256)
gemm_bf16_kernel(const __nv_bfloat16* __restrict__ A,
                 const __nv_bfloat16* __restrict__ Bw,
                 const float* __restrict__ bias,
                 __nv_bfloat16* __restrict__ O, int ldO)
{
    extern __shared__ char smem[];
    const uint32_t sb = smem_u32(smem);
    const int tid = threadIdx.x, lane = tid & 31, wid = tid >> 5;
    const int m0 = blockIdx.y * BM, n0 = blockIdx.x * BN;
    const int mbase = (wid & 3) * 32, nbase = (wid >> 2) * 64;

    const int ldr = tid >> 1;
    const int c0c = (tid & 1) * 2;
    const int lsw = (ldr >> 1) & 3;
    const uint64_t gA = (uint64_t)__cvta_generic_to_global(A) +
                        ((size_t)(m0 + ldr) * K + (size_t)c0c * 8) * 2;
    const uint64_t gB = (uint64_t)__cvta_generic_to_global(Bw) +
                        ((size_t)(n0 + ldr) * K + (size_t)c0c * 8) * 2;
    const uint32_t dA0 = sb + ldr * 64 + (((c0c)     ^ lsw) << 4);
    const uint32_t dA1 = sb + ldr * 64 + (((c0c + 1) ^ lsw) << 4);
    const uint32_t dB0 = dA0 + STG_A;
    const uint32_t dB1 = dA1 + STG_A;

    auto issue = [&](int c) {
        const uint32_t o = (uint32_t)(c & 3) * STG;
        const uint64_t ga = gA + (size_t)c * BK * 2;
        const uint64_t gb = gB + (size_t)c * BK * 2;
        asm volatile(
            "cp.async.cg.shared.global [%0], [%1], 16;\n\t"
            "cp.async.cg.shared.global [%2], [%3], 16;\n\t"
            "cp.async.cg.shared.global [%4], [%5], 16;\n\t"
            "cp.async.cg.shared.global [%6], [%7], 16;\n\t"
            :: "r"(dA0 + o), "l"(ga), "r"(dA1 + o), "l"(ga + 16),
               "r"(dB0 + o), "l"(gb), "r"(dB1 + o), "l"(gb + 16)
            : "memory");
        asm volatile("cp.async.commit_group;" ::: "memory");
    };

    const int rA0 = mbase + (lane & 15);
    const int rA1 = rA0 + 16;
    const uint32_t aOff0 = sb + rA0 * 64;
    const uint32_t aOff1 = sb + rA1 * 64;
    const int aSw0 = (rA0 >> 1) & 3, aSw1 = (rA1 >> 1) & 3;
    const int hA = lane >> 4;
    const int rBb = nbase + ((lane >> 4) << 3) + (lane & 7);
    const int hB = (lane >> 3) & 1;
    uint32_t bOff[4];
    int bSw[4];
#pragma unroll
    for (int jj = 0; jj < 4; jj++) {
        const int rB = rBb + 16 * jj;
        bOff[jj] = sb + STG_A + rB * 64;
        bSw[jj] = (rB >> 1) & 3;
    }

    float acc[2][8][4];
#pragma unroll
    for (int i = 0; i < 2; i++)
#pragma unroll
        for (int j = 0; j < 8; j++)
#pragma unroll
            for (int r = 0; r < 4; r++) acc[i][j][r] = 0.f;

    issue(0); issue(1); issue(2);

    const int NC = K / BK;
#pragma unroll 1
    for (int c = 0; c < NC; c++) {
        asm volatile("cp.async.wait_group 2;" ::: "memory");
        __syncthreads();
        if (c + 3 < NC) issue(c + 3);
        else asm volatile("cp.async.commit_group;" ::: "memory");

        const uint32_t bb = (uint32_t)(c & 3) * STG;
#pragma unroll
        for (int kk = 0; kk < 2; kk++) {
            uint32_t af0[4], af1[4], bf[4][4];
            const int ca = kk * 2 + hA;
            ldmx4(af0, bb + aOff0 + ((ca ^ aSw0) << 4));
            ldmx4(af1, bb + aOff1 + ((ca ^ aSw1) << 4));
            const int cb = kk * 2 + hB;
#pragma unroll
            for (int jj = 0; jj < 4; jj++)
                ldmx4(bf[jj], bb + bOff[jj] + ((cb ^ bSw[jj]) << 4));
#pragma unroll
            for (int j = 0; j < 8; j++) {
                const uint32_t b0 = bf[j >> 1][(j & 1) * 2];
                const uint32_t b1v = bf[j >> 1][(j & 1) * 2 + 1];
                mma16816(acc[0][j], af0, b0, b1v);
                mma16816(acc[1][j], af1, b0, b1v);
            }
        }
    }

    __syncthreads();
    const int qr = lane >> 2;
    __nv_bfloat16* st = (__nv_bfloat16*)smem;
#pragma unroll
    for (int j = 0; j < 8; j++) {
        const int nb = nbase + 8 * j + (lane & 3) * 2;
        const float2 bs = *(const float2*)(bias + n0 + nb);
#pragma unroll
        for (int i = 0; i < 2; i++) {
            float v0 = acc[i][j][0] + bs.x, v1 = acc[i][j][1] + bs.y;
            float v2 = acc[i][j][2] + bs.x, v3 = acc[i][j][3] + bs.y;
            if (RELU) {
                v0 = fmaxf(v0, 0.f); v1 = fmaxf(v1, 0.f);
                v2 = fmaxf(v2, 0.f); v3 = fmaxf(v3, 0.f);
            }
            const int mr = mbase + 16 * i + qr;
            *(__nv_bfloat162*)(st + mr * 136 + nb) = __floats2bfloat162_rn(v0, v1);
            *(__nv_bfloat162*)(st + (mr + 8) * 136 + nb) = __floats2bfloat162_rn(v2, v3);
        }
    }
    __syncthreads();
#pragma unroll
    for (int v = 0; v < 8; v++) {
        const int idx = tid + v * 256;
        const int row = idx >> 4, c8 = (idx & 15) * 8;
        *(uint4*)(O + (size_t)(m0 + row) * ldO + n0 + c8) =
            *(const uint4*)(st + row * 136 + c8);
    }
}

// ---------------- screened gumbel + argmax (unchanged, proven) --------------
__global__ void __launch_bounds__(256) argmax_kernel(
    const float* __restrict__ gumbel_u, float* __restrict__ idx_out_f)
{
    const int warp = (blockIdx.x * blockDim.x + threadIdx.x) >> 5;
    const int lane = threadIdx.x & 31;
    if (warp >= N_TOK * 2) return;
    const int n = warp >> 1, g = warp & 1;
    const __nv_bfloat16* lrow = g_lb + (size_t)n * CODE + g * CODE_G;
    const float* urow = gumbel_u + (size_t)n * CODE + g * CODE_G;

    float u[10], l[10];
#pragma unroll
    for (int j = 0; j < 10; j++) {
        u[j] = urow[lane + 32 * j];
        l[j] = __bfloat162float(lrow[lane + 32 * j]);
    }
    float umax = u[0], lmax = l[0], lmin = l[0];
#pragma unroll
    for (int j = 1; j < 10; j++) {
        umax = fmaxf(umax, u[j]);
        lmax = fmaxf(lmax, l[j]);
        lmin = fminf(lmin, l[j]);
    }
#pragma unroll
    for (int off = 16; off > 0; off >>= 1) {
        umax = fmaxf(umax, __shfl_xor_sync(0xffffffffu, umax, off));
        lmax = fmaxf(lmax, __shfl_xor_sync(0xffffffffu, lmax, off));
        lmin = fminf(lmin, __shfl_xor_sync(0xffffffffu, lmin, off));
    }
    const float gU   = -__logf(-__logf(umax + EPS) + EPS);
    const float gthr = gU - (lmax - lmin) - DELTA - 0.02f;
    const float wv   = __expf(-gthr);
    float uthr = __expf(-(wv - EPS)) - EPS;
    uthr = uthr - fabsf(uthr) * 4e-6f - 1e-7f;

    float b1v = -INFINITY, b2v = -INFINITY;
    int bi = 0x7fffffff;
#pragma unroll
    for (int j = 0; j < 10; j++) {
        if (u[j] >= uthr) {
            const float gn = -__logf(-__logf(u[j] + EPS) + EPS);
            const float v = l[j] + gn;
            if (v > b1v) { b2v = b1v; b1v = v; bi = lane + 32 * j; }
            else if (v > b2v) b2v = v;
        }
    }
#pragma unroll
    for (int off = 16; off > 0; off >>= 1) {
        float o1 = __shfl_down_sync(0xffffffffu, b1v, off);
        float o2 = __shfl_down_sync(0xffffffffu, b2v, off);
        int   oi = __shfl_down_sync(0xffffffffu, bi, off);
        if (o1 > b1v || (o1 == b1v && oi < bi)) {
            b2v = fmaxf(b1v, o2); b1v = o1; bi = oi;
        } else {
            b2v = fmaxf(b2v, o1);
        }
    }
    if (lane == 0) {
        g_idx[warp] = bi;
        idx_out_f[warp] = (float)bi;
        if (b1v - b2v < DELTA) {
            int p = atomicAdd(&g_fixcnt, 1);
            if (p < FIXMAX) g_fixlist[p] = warp;
        }
    }
}

// ---------------- fixup v4: batched skinny GEMM pipeline --------------------
// Phase 0: gather exact fp32 x rows for flagged slots.
__global__ void __launch_bounds__(256) fix_gather_x(const float* __restrict__ series)
{
    const int cnt = min(g_fixcnt, FIXMAX);
    const int total = cnt * FEAT_I;
    for (int idx = blockIdx.x * 256 + threadIdx.x; idx < total;
         idx += gridDim.x * 256) {
        const int s = idx >> 9, k = idx & 511;
        const int n = g_fixlist[s] >> 1;
        const int b = n >> 12, t = n & 4095;
        g_fixx[idx] = series[((size_t)b * FEAT_I + k) * T_SZ + t];
    }
}

// Phase 1/2: O[s][n] = (X[s][.] . W[.][n]) + bias[n], optional relu.
// Tile 64 slots x 64 cols; weights read once per slot-tile (not per slot).
template<int K, int NF, bool RELU>
__global__ void __launch_bounds__(256) fix_gemm(
    const float* __restrict__ X, const float* __restrict__ W,
    const float* __restrict__ bias, float* __restrict__ O)
{
    const int cnt = min(g_fixcnt, FIXMAX);
    const int m0 = blockIdx.y * 64;
    if (m0 >= cnt) return;
    const int n0 = blockIdx.x * 64;

    __shared__ float xs[64][17];
    __shared__ float ws[16][65];
    const int tid = threadIdx.x;
    const int tx = tid & 15, ty = tid >> 4;

    float acc[4][4];
#pragma unroll
    for (int i = 0; i < 4; i++)
#pragma unroll
        for (int j = 0; j < 4; j++) acc[i][j] = 0.f;

    const int xm = tid >> 2, xk = (tid & 3) * 4;
    const int wk = tid >> 4, wn = (tid & 15) * 4;

    for (int k0 = 0; k0 < K; k0 += 16) {
        float4 xv = *(const float4*)(X + (size_t)(m0 + xm) * K + k0 + xk);
        float4 wv = *(const float4*)(W + (size_t)(k0 + wk) * NF + n0 + wn);
        xs[xm][xk] = xv.x; xs[xm][xk + 1] = xv.y;
        xs[xm][xk + 2] = xv.z; xs[xm][xk + 3] = xv.w;
        ws[wk][wn] = wv.x; ws[wk][wn + 1] = wv.y;
        ws[wk][wn + 2] = wv.z; ws[wk][wn + 3] = wv.w;
        __syncthreads();
#pragma unroll
        for (int kk = 0; kk < 16; kk++) {
            float a[4], bv[4];
#pragma unroll
            for (int i = 0; i < 4; i++) a[i] = xs[ty * 4 + i][kk];
#pragma unroll
            for (int j = 0; j < 4; j++) bv[j] = ws[kk][tx * 4 + j];
#pragma unroll
            for (int i = 0; i < 4; i++)
#pragma unroll
                for (int j = 0; j < 4; j++)
                    acc[i][j] = fmaf(a[i], bv[j], acc[i][j]);
        }
        __syncthreads();
    }

#pragma unroll
    for (int i = 0; i < 4; i++) {
        const int m = m0 + ty * 4 + i;
        if (m < cnt) {
#pragma unroll
            for (int j = 0; j < 4; j++) {
                const int nn = n0 + tx * 4 + j;
                float v = acc[i][j] + bias[nn];
                if (RELU) v = fmaxf(v, 0.f);
                O[(size_t)m * NF + nn] = v;
            }
        }
    }
}

// Phase 3: exact argmax (fp32 logits + exact logf gumbel) per flagged slot.
__global__ void __launch_bounds__(256) fix_argmax(
    const float* __restrict__ gumbel_u, float* __restrict__ idx_out_f)
{
    const int s = (blockIdx.x * blockDim.x + threadIdx.x) >> 5;
    const int lane = threadIdx.x & 31;
    const int cnt = min(g_fixcnt, FIXMAX);
    if (s >= cnt) return;
    const int slot = g_fixlist[s];
    const int n = slot >> 1, g = slot & 1;
    const float* lrow = g_fixl + (size_t)s * CODE + g * CODE_G;
    const float* urow = gumbel_u + (size_t)n * CODE + g * CODE_G;

    float bv = -INFINITY;
    int bi = 0x7fffffff;
#pragma unroll
    for (int c = lane; c < CODE_G; c += 32) {
        const float u = urow[c];
        const float v = lrow[c] + (-logf(-logf(u + EPS) + EPS));
        if (v > bv) { bv = v; bi = c; }
    }
#pragma unroll
    for (int off = 16; off > 0; off >>= 1) {
        float ov = __shfl_down_sync(0xffffffffu, bv, off);
        int   oi = __shfl_down_sync(0xffffffffu, bi, off);
        if (ov > bv || (ov == bv && oi < bi)) { bv = ov; bi = oi; }
    }
    if (lane == 0) {
        g_idx[slot] = bi;
        idx_out_f[slot] = (float)bi;
    }
}

// ---------------- gather: tiled, coalesced; resets fix counter --------------
__global__ void __launch_bounds__(256) gather_kernel(
    const float* __restrict__ codebook, float* __restrict__ out)
{
    __shared__ float cb[32 * 257];
    __shared__ int   sidx[32];
    const int tid = threadIdx.x;
    if (blockIdx.x == 0 && tid == 0) g_fixcnt = 0;
    const int t0 = (blockIdx.x & 127) * 32;
    const int g  = (blockIdx.x >> 7) & 1;
    const int b  = blockIdx.x >> 8;

    if (tid < 32)
        sidx[tid] = g_idx[((b << 12) + t0 + tid) * 2 + g];
    __syncthreads();

#pragma unroll
    for (int it = 0; it < 8; it++) {
        const int j = tid + it * 256;
        const int row = j >> 6, c4 = (j & 63) * 4;
        float4 v = *(const float4*)(codebook + (((size_t)g * CODE_G + sidx[row]) << 8) + c4);
        float* p = cb + row * 257 + c4;
        p[0] = v.x; p[1] = v.y; p[2] = v.z; p[3] = v.w;
    }
    __syncthreads();

#pragma unroll
    for (int it = 0; it < 8; it++) {
        const int j = tid + it * 256;
        const int f = j >> 3, t4 = (j & 7) * 4;
        float4 v;
        v.x = cb[(t4 + 0) * 257 + f];
        v.y = cb[(t4 + 1) * 257 + f];
        v.z = cb[(t4 + 2) * 257 + f];
        v.w = cb[(t4 + 3) * 257 + f];
        *(float4*)(out + ((size_t)(b * 512 + g * 256 + f) << 12) + t0 + t4) = v;
    }
}

// ---------------------------------------------------------------------------
extern "C" void kernel_launch(void* const* d_in, const int* in_sizes, int n_in,
                              void* d_out, int out_size)
{
    const float* series   = (const float*)d_in[0];
    const float* gumbel_u = (const float*)d_in[1];
    const float* W1       = (const float*)d_in[2];
    const float* b1       = (const float*)d_in[3];
    const float* W2       = (const float*)d_in[4];
    const float* b2       = (const float*)d_in[5];
    const float* codebook = (const float*)d_in[6];
    float* out = (float*)d_out;
    float* idx_out = out + ((size_t)out_size - (size_t)N_TOK * 2);

    __nv_bfloat16 *xb, *w1b, *w2b, *hb, *lb;
    cudaGetSymbolAddress((void**)&xb,  g_xb);
    cudaGetSymbolAddress((void**)&w1b, g_w1b);
    cudaGetSymbolAddress((void**)&w2b, g_w2b);
    cudaGetSymbolAddress((void**)&hb,  g_hb);
    cudaGetSymbolAddress((void**)&lb,  g_lb);
    float *fx, *fh, *fl;
    cudaGetSymbolAddress((void**)&fx, g_fixx);
    cudaGetSymbolAddress((void**)&fh, g_fixh);
    cudaGetSymbolAddress((void**)&fl, g_fixl);

    cudaFuncSetAttribute(gemm_bf16_kernel<FEAT_I, true>,
                         cudaFuncAttributeMaxDynamicSharedMemorySize, PIPE_SMEM);
    cudaFuncSetAttribute(gemm_bf16_kernel<H_DIM, false>,
                         cudaFuncAttributeMaxDynamicSharedMemorySize, PIPE_SMEM);

    transpose_bf16_kernel<<<dim3(T_SZ / 32, FEAT_I / 32, B_SZ), dim3(32, 8)>>>(
        series, xb, FEAT_I, T_SZ, (size_t)FEAT_I * T_SZ, (size_t)T_SZ * FEAT_I);
    transpose_bf16_kernel<<<dim3(H_DIM / 32, FEAT_I / 32, 1), dim3(32, 8)>>>(
        W1, w1b, FEAT_I, H_DIM, 0, 0);
    transpose_bf16_kernel<<<dim3(CODE / 32, H_DIM / 32, 1), dim3(32, 8)>>>(
        W2, w2b, H_DIM, CODE, 0, 0);

    gemm_bf16_kernel<FEAT_I, true><<<dim3(H_DIM / BN, N_TOK / BM), 256, PIPE_SMEM>>>(
        xb, w1b, b1, hb, H_DIM);
    gemm_bf16_kernel<H_DIM, false><<<dim3(CODE / BN, N_TOK / BM), 256, PIPE_SMEM>>>(
        hb, w2b, b2, lb, CODE);

    argmax_kernel<<<(N_TOK * 2 * 32) / 256, 256>>>(gumbel_u, idx_out);

    // batched exact fixup
    fix_gather_x<<<128, 256>>>(series);
    fix_gemm<FEAT_I, H_DIM, true><<<dim3(H_DIM / 64, FIXMAX / 64), 256>>>(
        fx, W1, b1, fh);
    fix_gemm<H_DIM, CODE, false><<<dim3(CODE / 64, FIXMAX / 64), 256>>>(
        fh, W2, b2, fl);
    fix_argmax<<<FIXMAX / 8, 256>>>(gumbel_u, idx_out);

    gather_kernel<<<B_SZ * 2 * (T_SZ / 32), 256>>>(codebook, out);
}

// round 17
// speedup vs baseline: 3.9980x; 1.0196x over previous
#include <cuda_runtime.h>
#include <cuda_bf16.h>
#include <math.h>
#include <stdint.h>

#define FEAT_I 512
#define H_DIM  1024
#define CODE   640
#define CODE_G 320
#define B_SZ   8
#define T_SZ   4096
#define N_TOK  32768

#define DELTA   0.008f
#define EPS     1e-10f
#define FIXMAX  16384

// ---------------- scratch (static device globals; no allocation) -----------
__device__ __nv_bfloat16 g_xb[(size_t)N_TOK * FEAT_I];
__device__ __nv_bfloat16 g_w1b[(size_t)H_DIM * FEAT_I];
__device__ __nv_bfloat16 g_w2b[(size_t)CODE * H_DIM];
__device__ __nv_bfloat16 g_hb[(size_t)N_TOK * H_DIM];
__device__ __nv_bfloat16 g_lb[(size_t)N_TOK * CODE];
__device__ int g_idx[N_TOK * 2];
__device__ int g_fixcnt;
__device__ int g_fixlist[FIXMAX];
__device__ float g_fixx[(size_t)FIXMAX * FEAT_I];
__device__ float g_fixh[(size_t)FIXMAX * H_DIM];
__device__ float g_fixl[(size_t)FIXMAX * CODE];

// ---------------- helpers ---------------------------------------------------
__device__ __forceinline__ uint32_t smem_u32(const void* p) {
    uint32_t a;
    asm("{ .reg .u64 t; cvta.to.shared.u64 t, %1; cvt.u32.u64 %0, t; }"
        : "=r"(a) : "l"(p));
    return a;
}

__device__ __forceinline__ void ldmx4(uint32_t* r, uint32_t addr) {
    asm volatile("ldmatrix.sync.aligned.m8n8.x4.shared.b16 {%0,%1,%2,%3}, [%4];"
                 : "=r"(r[0]), "=r"(r[1]), "=r"(r[2]), "=r"(r[3]) : "r"(addr));
}

__device__ __forceinline__ void mma16816(float* d, const uint32_t* a,
                                         uint32_t b0, uint32_t b1) {
    asm volatile(
        "mma.sync.aligned.m16n8k16.row.col.f32.bf16.bf16.f32 "
        "{%0,%1,%2,%3}, {%4,%5,%6,%7}, {%8,%9}, {%0,%1,%2,%3};"
        : "+f"(d[0]), "+f"(d[1]), "+f"(d[2]), "+f"(d[3])
        : "r"(a[0]), "r"(a[1]), "r"(a[2]), "r"(a[3]), "r"(b0), "r"(b1));
}

// ---------------- transpose fp32 -> bf16: OUT[c][r] = IN[r][c] --------------
__global__ void transpose_bf16_kernel(const float* __restrict__ in,
                                      __nv_bfloat16* __restrict__ out,
                                      int R, int C, size_t ibs, size_t obs)
{
    __shared__ float tile[32][33];
    in += (size_t)blockIdx.z * ibs;
    const size_t ob = (size_t)blockIdx.z * obs;
    const int c0 = blockIdx.x * 32, r0 = blockIdx.y * 32;
    const int tx = threadIdx.x, ty = threadIdx.y;
#pragma unroll
    for (int j = 0; j < 4; j++)
        tile[ty + 8 * j][tx] = in[(size_t)(r0 + ty + 8 * j) * C + c0 + tx];
    __syncthreads();
#pragma unroll
    for (int j = 0; j < 4; j++)
        out[ob + (size_t)(c0 + ty + 8 * j) * R + r0 + tx] =
            __float2bfloat16(tile[tx][ty + 8 * j]);
}

// ---------------- bf16 HMMA GEMM: BK=64, 128B rows, c^(r&7) swizzle ---------
#define BM 128
#define BN 128
#define BK 64
#define STG_A  16384           // 128 rows * 128B
#define STG    32768
#define NSTAGE 3
#define PIPE_SMEM (NSTAGE * STG)   // 98304

template<int K, bool RELU>
__global__ void __launch_bounds__(256, 2)
gemm_bf16_kernel(const __nv_bfloat16* __restrict__ A,
                 const __nv_bfloat16* __restrict__ Bw,
                 const float* __restrict__ bias,
                 __nv_bfloat16* __restrict__ O, int ldO)
{
    extern __shared__ char smem[];
    const uint32_t sb = smem_u32(smem);
    const int tid = threadIdx.x, lane = tid & 31, wid = tid >> 5;
    const int m0 = blockIdx.y * BM, n0 = blockIdx.x * BN;
    const int mbase = (wid & 3) * 32, nbase = (wid >> 2) * 64;

    // ---- cp.async: thread -> row = tid>>1, chunks hc..hc+3 (16B each) ----
    const int ldr = tid >> 1;
    const int hc  = (tid & 1) * 4;
    const int lsw = ldr & 7;
    const uint64_t gA = (uint64_t)__cvta_generic_to_global(A) +
                        ((size_t)(m0 + ldr) * K + (size_t)hc * 8) * 2;
    const uint64_t gB = (uint64_t)__cvta_generic_to_global(Bw) +
                        ((size_t)(n0 + ldr) * K + (size_t)hc * 8) * 2;
    uint32_t sA[4], sB[4];
#pragma unroll
    for (int j = 0; j < 4; j++) {
        sA[j] = sb + ldr * 128 + (((hc + j) ^ lsw) << 4);
        sB[j] = sA[j] + STG_A;
    }

    auto issue = [&](int c, int slot) {
        const uint32_t o = (uint32_t)slot * STG;
        const uint64_t ga = gA + (size_t)c * (BK * 2);
        const uint64_t gb = gB + (size_t)c * (BK * 2);
#pragma unroll
        for (int j = 0; j < 4; j++)
            asm volatile("cp.async.cg.shared.global [%0], [%1], 16;"
                         :: "r"(sA[j] + o), "l"(ga + j * 16) : "memory");
#pragma unroll
        for (int j = 0; j < 4; j++)
            asm volatile("cp.async.cg.shared.global [%0], [%1], 16;"
                         :: "r"(sB[j] + o), "l"(gb + j * 16) : "memory");
        asm volatile("cp.async.commit_group;" ::: "memory");
    };

    // ---- ldmatrix lane addressing ----
    const int rA0 = mbase + (lane & 15);
    const uint32_t aB0 = sb + rA0 * 128;
    const uint32_t aB1 = aB0 + 16 * 128;
    const int swA = rA0 & 7;
    const int hA = lane >> 4;
    const int rBb = nbase + ((lane >> 4) << 3) + (lane & 7);
    const uint32_t bB0 = sb + STG_A + rBb * 128;
    const int swB = rBb & 7;
    const int hB = (lane >> 3) & 1;

    float acc[2][8][4];
#pragma unroll
    for (int i = 0; i < 2; i++)
#pragma unroll
        for (int j = 0; j < 8; j++)
#pragma unroll
            for (int r = 0; r < 4; r++) acc[i][j][r] = 0.f;

    issue(0, 0); issue(1, 1);

    const int NC = K / BK;
    int slot = 2;
#pragma unroll 1
    for (int c = 0; c < NC; c++) {
        asm volatile("cp.async.wait_group 1;" ::: "memory");
        __syncthreads();
        if (c + 2 < NC) issue(c + 2, slot);
        else asm volatile("cp.async.commit_group;" ::: "memory");
        const int cur = (slot + 1 < NSTAGE) ? (slot + 1) : 0;  // (c % 3)
        slot = cur;  // next issue overwrites the buffer we're about to read
        const uint32_t bb = (uint32_t)((c == 0) ? 0 : ((c - (c / 3) * 3))) * 0 +
                            (uint32_t)(c % 3) * STG;

#pragma unroll
        for (int kk = 0; kk < 4; kk++) {
            uint32_t af0[4], af1[4], bf[4][4];
            const int ca = 2 * kk + hA;
            ldmx4(af0, bb + aB0 + ((ca ^ swA) << 4));
            ldmx4(af1, bb + aB1 + ((ca ^ swA) << 4));
            const int cb = 2 * kk + hB;
            const uint32_t bO = ((cb ^ swB) << 4);
#pragma unroll
            for (int jj = 0; jj < 4; jj++)
                ldmx4(bf[jj], bb + bB0 + jj * (16 * 128) + bO);
#pragma unroll
            for (int j = 0; j < 8; j++) {
                const uint32_t b0 = bf[j >> 1][(j & 1) * 2];
                const uint32_t b1v = bf[j >> 1][(j & 1) * 2 + 1];
                mma16816(acc[0][j], af0, b0, b1v);
                mma16816(acc[1][j], af1, b0, b1v);
            }
        }
    }

    // epilogue: bias (+relu), stage bf16 in smem, 16B-coalesced stores
    __syncthreads();
    const int qr = lane >> 2;
    __nv_bfloat16* st = (__nv_bfloat16*)smem;
#pragma unroll
    for (int j = 0; j < 8; j++) {
        const int nb = nbase + 8 * j + (lane & 3) * 2;
        const float2 bs = *(const float2*)(bias + n0 + nb);
#pragma unroll
        for (int i = 0; i < 2; i++) {
            float v0 = acc[i][j][0] + bs.x, v1 = acc[i][j][1] + bs.y;
            float v2 = acc[i][j][2] + bs.x, v3 = acc[i][j][3] + bs.y;
            if (RELU) {
                v0 = fmaxf(v0, 0.f); v1 = fmaxf(v1, 0.f);
                v2 = fmaxf(v2, 0.f); v3 = fmaxf(v3, 0.f);
            }
            const int mr = mbase + 16 * i + qr;
            *(__nv_bfloat162*)(st + mr * 136 + nb) = __floats2bfloat162_rn(v0, v1);
            *(__nv_bfloat162*)(st + (mr + 8) * 136 + nb) = __floats2bfloat162_rn(v2, v3);
        }
    }
    __syncthreads();
#pragma unroll
    for (int v = 0; v < 8; v++) {
        const int idx = tid + v * 256;
        const int row = idx >> 4, c8 = (idx & 15) * 8;
        *(uint4*)(O + (size_t)(m0 + row) * ldO + n0 + c8) =
            *(const uint4*)(st + row * 136 + c8);
    }
}

// ---------------- screened gumbel + argmax (unchanged, proven) --------------
__global__ void __launch_bounds__(256) argmax_kernel(
    const float* __restrict__ gumbel_u, float* __restrict__ idx_out_f)
{
    const int warp = (blockIdx.x * blockDim.x + threadIdx.x) >> 5;
    const int lane = threadIdx.x & 31;
    if (warp >= N_TOK * 2) return;
    const int n = warp >> 1, g = warp & 1;
    const __nv_bfloat16* lrow = g_lb + (size_t)n * CODE + g * CODE_G;
    const float* urow = gumbel_u + (size_t)n * CODE + g * CODE_G;

    float u[10], l[10];
#pragma unroll
    for (int j = 0; j < 10; j++) {
        u[j] = urow[lane + 32 * j];
        l[j] = __bfloat162float(lrow[lane + 32 * j]);
    }
    float umax = u[0], lmax = l[0], lmin = l[0];
#pragma unroll
    for (int j = 1; j < 10; j++) {
        umax = fmaxf(umax, u[j]);
        lmax = fmaxf(lmax, l[j]);
        lmin = fminf(lmin, l[j]);
    }
#pragma unroll
    for (int off = 16; off > 0; off >>= 1) {
        umax = fmaxf(umax, __shfl_xor_sync(0xffffffffu, umax, off));
        lmax = fmaxf(lmax, __shfl_xor_sync(0xffffffffu, lmax, off));
        lmin = fminf(lmin, __shfl_xor_sync(0xffffffffu, lmin, off));
    }
    const float gU   = -__logf(-__logf(umax + EPS) + EPS);
    const float gthr = gU - (lmax - lmin) - DELTA - 0.02f;
    const float wv   = __expf(-gthr);
    float uthr = __expf(-(wv - EPS)) - EPS;
    uthr = uthr - fabsf(uthr) * 4e-6f - 1e-7f;

    float b1v = -INFINITY, b2v = -INFINITY;
    int bi = 0x7fffffff;
#pragma unroll
    for (int j = 0; j < 10; j++) {
        if (u[j] >= uthr) {
            const float gn = -__logf(-__logf(u[j] + EPS) + EPS);
            const float v = l[j] + gn;
            if (v > b1v) { b2v = b1v; b1v = v; bi = lane + 32 * j; }
            else if (v > b2v) b2v = v;
        }
    }
#pragma unroll
    for (int off = 16; off > 0; off >>= 1) {
        float o1 = __shfl_down_sync(0xffffffffu, b1v, off);
        float o2 = __shfl_down_sync(0xffffffffu, b2v, off);
        int   oi = __shfl_down_sync(0xffffffffu, bi, off);
        if (o1 > b1v || (o1 == b1v && oi < bi)) {
            b2v = fmaxf(b1v, o2); b1v = o1; bi = oi;
        } else {
            b2v = fmaxf(b2v, o1);
        }
    }
    if (lane == 0) {
        g_idx[warp] = bi;
        idx_out_f[warp] = (float)bi;
        if (b1v - b2v < DELTA) {
            int p = atomicAdd(&g_fixcnt, 1);
            if (p < FIXMAX) g_fixlist[p] = warp;
        }
    }
}

// ---------------- fixup: batched skinny GEMM pipeline (proven) --------------
__global__ void __launch_bounds__(256) fix_gather_x(const float* __restrict__ series)
{
    const int cnt = min(g_fixcnt, FIXMAX);
    const int total = cnt * FEAT_I;
    for (int idx = blockIdx.x * 256 + threadIdx.x; idx < total;
         idx += gridDim.x * 256) {
        const int s = idx >> 9, k = idx & 511;
        const int n = g_fixlist[s] >> 1;
        const int b = n >> 12, t = n & 4095;
        g_fixx[idx] = series[((size_t)b * FEAT_I + k) * T_SZ + t];
    }
}

template<int K, int NF, bool RELU>
__global__ void __launch_bounds__(256) fix_gemm(
    const float* __restrict__ X, const float* __restrict__ W,
    const float* __restrict__ bias, float* __restrict__ O)
{
    const int cnt = min(g_fixcnt, FIXMAX);
    const int m0 = blockIdx.y * 64;
    if (m0 >= cnt) return;
    const int n0 = blockIdx.x * 64;

    __shared__ float xs[64][17];
    __shared__ float ws[16][65];
    const int tid = threadIdx.x;
    const int tx = tid & 15, ty = tid >> 4;

    float acc[4][4];
#pragma unroll
    for (int i = 0; i < 4; i++)
#pragma unroll
        for (int j = 0; j < 4; j++) acc[i][j] = 0.f;

    const int xm = tid >> 2, xk = (tid & 3) * 4;
    const int wk = tid >> 4, wn = (tid & 15) * 4;

    for (int k0 = 0; k0 < K; k0 += 16) {
        float4 xv = *(const float4*)(X + (size_t)(m0 + xm) * K + k0 + xk);
        float4 wv = *(const float4*)(W + (size_t)(k0 + wk) * NF + n0 + wn);
        xs[xm][xk] = xv.x; xs[xm][xk + 1] = xv.y;
        xs[xm][xk + 2] = xv.z; xs[xm][xk + 3] = xv.w;
        ws[wk][wn] = wv.x; ws[wk][wn + 1] = wv.y;
        ws[wk][wn + 2] = wv.z; ws[wk][wn + 3] = wv.w;
        __syncthreads();
#pragma unroll
        for (int kk = 0; kk < 16; kk++) {
            float a[4], bv[4];
#pragma unroll
            for (int i = 0; i < 4; i++) a[i] = xs[ty * 4 + i][kk];
#pragma unroll
            for (int j = 0; j < 4; j++) bv[j] = ws[kk][tx * 4 + j];
#pragma unroll
            for (int i = 0; i < 4; i++)
#pragma unroll
                for (int j = 0; j < 4; j++)
                    acc[i][j] = fmaf(a[i], bv[j], acc[i][j]);
        }
        __syncthreads();
    }

#pragma unroll
    for (int i = 0; i < 4; i++) {
        const int m = m0 + ty * 4 + i;
        if (m < cnt) {
#pragma unroll
            for (int j = 0; j < 4; j++) {
                const int nn = n0 + tx * 4 + j;
                float v = acc[i][j] + bias[nn];
                if (RELU) v = fmaxf(v, 0.f);
                O[(size_t)m * NF + nn] = v;
            }
        }
    }
}

__global__ void __launch_bounds__(256) fix_argmax(
    const float* __restrict__ gumbel_u, float* __restrict__ idx_out_f)
{
    const int s = (blockIdx.x * blockDim.x + threadIdx.x) >> 5;
    const int lane = threadIdx.x & 31;
    const int cnt = min(g_fixcnt, FIXMAX);
    if (s >= cnt) return;
    const int slot = g_fixlist[s];
    const int n = slot >> 1, g = slot & 1;
    const float* lrow = g_fixl + (size_t)s * CODE + g * CODE_G;
    const float* urow = gumbel_u + (size_t)n * CODE + g * CODE_G;

    float bv = -INFINITY;
    int bi = 0x7fffffff;
#pragma unroll
    for (int c = lane; c < CODE_G; c += 32) {
        const float u = urow[c];
        const float v = lrow[c] + (-logf(-logf(u + EPS) + EPS));
        if (v > bv) { bv = v; bi = c; }
    }
#pragma unroll
    for (int off = 16; off > 0; off >>= 1) {
        float ov = __shfl_down_sync(0xffffffffu, bv, off);
        int   oi = __shfl_down_sync(0xffffffffu, bi, off);
        if (ov > bv || (ov == bv && oi < bi)) { bv = ov; bi = oi; }
    }
    if (lane == 0) {
        g_idx[slot] = bi;
        idx_out_f[slot] = (float)bi;
    }
}

// ---------------- gather: tiled, coalesced; resets fix counter --------------
__global__ void __launch_bounds__(256) gather_kernel(
    const float* __restrict__ codebook, float* __restrict__ out)
{
    __shared__ float cb[32 * 257];
    __shared__ int   sidx[32];
    const int tid = threadIdx.x;
    if (blockIdx.x == 0 && tid == 0) g_fixcnt = 0;
    const int t0 = (blockIdx.x & 127) * 32;
    const int g  = (blockIdx.x >> 7) & 1;
    const int b  = blockIdx.x >> 8;

    if (tid < 32)
        sidx[tid] = g_idx[((b << 12) + t0 + tid) * 2 + g];
    __syncthreads();

#pragma unroll
    for (int it = 0; it < 8; it++) {
        const int j = tid + it * 256;
        const int row = j >> 6, c4 = (j & 63) * 4;
        float4 v = *(const float4*)(codebook + (((size_t)g * CODE_G + sidx[row]) << 8) + c4);
        float* p = cb + row * 257 + c4;
        p[0] = v.x; p[1] = v.y; p[2] = v.z; p[3] = v.w;
    }
    __syncthreads();

#pragma unroll
    for (int it = 0; it < 8; it++) {
        const int j = tid + it * 256;
        const int f = j >> 3, t4 = (j & 7) * 4;
        float4 v;
        v.x = cb[(t4 + 0) * 257 + f];
        v.y = cb[(t4 + 1) * 257 + f];
        v.z = cb[(t4 + 2) * 257 + f];
        v.w = cb[(t4 + 3) * 257 + f];
        *(float4*)(out + ((size_t)(b * 512 + g * 256 + f) << 12) + t0 + t4) = v;
    }
}

// ---------------------------------------------------------------------------
extern "C" void kernel_launch(void* const* d_in, const int* in_sizes, int n_in,
                              void* d_out, int out_size)
{
    const float* series   = (const float*)d_in[0];
    const float* gumbel_u = (const float*)d_in[1];
    const float* W1       = (const float*)d_in[2];
    const float* b1       = (const float*)d_in[3];
    const float* W2       = (const float*)d_in[4];
    const float* b2       = (const float*)d_in[5];
    const float* codebook = (const float*)d_in[6];
    float* out = (float*)d_out;
    float* idx_out = out + ((size_t)out_size - (size_t)N_TOK * 2);

    __nv_bfloat16 *xb, *w1b, *w2b, *hb, *lb;
    cudaGetSymbolAddress((void**)&xb,  g_xb);
    cudaGetSymbolAddress((void**)&w1b, g_w1b);
    cudaGetSymbolAddress((void**)&w2b, g_w2b);
    cudaGetSymbolAddress((void**)&hb,  g_hb);
    cudaGetSymbolAddress((void**)&lb,  g_lb);
    float *fx, *fh, *fl;
    cudaGetSymbolAddress((void**)&fx, g_fixx);
    cudaGetSymbolAddress((void**)&fh, g_fixh);
    cudaGetSymbolAddress((void**)&fl, g_fixl);

    cudaFuncSetAttribute(gemm_bf16_kernel<FEAT_I, true>,
                         cudaFuncAttributeMaxDynamicSharedMemorySize, PIPE_SMEM);
    cudaFuncSetAttribute(gemm_bf16_kernel<H_DIM, false>,
                         cudaFuncAttributeMaxDynamicSharedMemorySize, PIPE_SMEM);

    transpose_bf16_kernel<<<dim3(T_SZ / 32, FEAT_I / 32, B_SZ), dim3(32, 8)>>>(
        series, xb, FEAT_I, T_SZ, (size_t)FEAT_I * T_SZ, (size_t)T_SZ * FEAT_I);
    transpose_bf16_kernel<<<dim3(H_DIM / 32, FEAT_I / 32, 1), dim3(32, 8)>>>(
        W1, w1b, FEAT_I, H_DIM, 0, 0);
    transpose_bf16_kernel<<<dim3(CODE / 32, H_DIM / 32, 1), dim3(32, 8)>>>(
        W2, w2b, H_DIM, CODE, 0, 0);

    gemm_bf16_kernel<FEAT_I, true><<<dim3(H_DIM / BN, N_TOK / BM), 256, PIPE_SMEM>>>(
        xb, w1b, b1, hb, H_DIM);
    gemm_bf16_kernel<H_DIM, false><<<dim3(CODE / BN, N_TOK / BM), 256, PIPE_SMEM>>>(
        hb, w2b, b2, lb, CODE);

    argmax_kernel<<<(N_TOK * 2 * 32) / 256, 256>>>(gumbel_u, idx_out);

    fix_gather_x<<<128, 256>>>(series);
    fix_gemm<FEAT_I, H_DIM, true><<<dim3(H_DIM / 64, FIXMAX / 64), 256>>>(
        fx, W1, b1, fh);
    fix_gemm<H_DIM, CODE, false><<<dim3(CODE / 64, FIXMAX / 64), 256>>>(
        fh, W2, b2, fl);
    fix_argmax<<<FIXMAX / 8, 256>>>(gumbel_u, idx_out);

    gather_kernel<<<B_SZ * 2 * (T_SZ / 32), 256>>>(codebook, out);
}